// round 1
// baseline (speedup 1.0000x reference)
#include <cuda_runtime.h>

// ---------------- problem constants ----------------
#define BSZ   4
#define NN    512
#define EMBD  64
#define INF   256          // IN_DIM
#define H1    128          // fc1 out (2*HD)
#define HE    64           // e1 out
#define NPAIR (NN*(NN-1))                 // 261632
#define PRED_OFF (BSZ*NN*NN)              // 1048576
#define EMB_OFF  (PRED_OFF + BSZ*NPAIR*2) // 3141632

// ---------------- device scratch (no allocs allowed) ----------------
__device__ float g_emb [BSZ*NN*EMBD];     // emb row-major   [b][n][k]
__device__ float g_embT[BSZ*EMBD*NN];     // emb transposed  [b][k][n]
__device__ float g_A   [BSZ*NN*HE];       // emb @ W1top     [b][n][h]

// ---------------- helpers: packed f32x2 FMA ----------------
__device__ __forceinline__ unsigned long long pack2(float a) {
    unsigned long long r;
    asm("mov.b64 %0, {%1, %1};" : "=l"(r) : "f"(a));
    return r;
}
__device__ __forceinline__ void fma2(unsigned long long& d,
                                     unsigned long long a,
                                     unsigned long long b) {
    asm("fma.rn.f32x2 %0, %1, %2, %0;" : "+l"(d) : "l"(a), "l"(b));
}
__device__ __forceinline__ void unpack2(unsigned long long v, float& lo, float& hi) {
    asm("mov.b64 {%0, %1}, %2;" : "=f"(lo), "=f"(hi) : "l"(v));
}

// =====================================================================
// Stage 1: node MLP.  h = leaky(x@fc1+b1); emb = leaky(h@fc2+b2);
//          A = emb @ e1_w[:64,:].  Writes emb (out + scratch), embT, A.
// Grid: 128 blocks x 256 threads, 16 nodes per block.
// =====================================================================
__global__ __launch_bounds__(256)
void stage1(const float* __restrict__ nf,
            const float* __restrict__ fc1w, const float* __restrict__ fc1b,
            const float* __restrict__ fc2w, const float* __restrict__ fc2b,
            const float* __restrict__ e1w,
            float* __restrict__ out)
{
    extern __shared__ float sm[];
    float* Xs = sm;             // 16*256 = 4096 floats
    float* Ws = Xs + 4096;      // up to 8192 floats (weight tile)
    float* Hs = Ws + 8192;      // 16*132 = 2112 floats (padded)
    float* Es = Hs + 2112;      // 16*64  = 1024 floats

    const int t  = threadIdx.x;
    const int nb = blockIdx.x * 16;          // first node of this block
    const int node = t >> 4;                 // 0..15
    const int sub  = t & 15;                 // 0..15

    // load X tile (flat copy, coalesced)
    #pragma unroll
    for (int r = 0; r < 16; r++)
        Xs[t + r*256] = nf[nb*INF + t + r*256];

    // ---- phase A: h = leaky(x @ fc1 + b1), per thread 8 h-outputs ----
    {
        const int hb = sub * 8;
        float acc[8];
        #pragma unroll
        for (int h = 0; h < 8; h++) acc[h] = 0.f;

        for (int kt = 0; kt < 4; kt++) {
            __syncthreads();
            #pragma unroll
            for (int r = 0; r < 32; r++)
                Ws[t + r*256] = fc1w[kt*64*H1 + t + r*256];
            __syncthreads();
            #pragma unroll
            for (int k = 0; k < 64; k++) {
                float x = Xs[node*INF + kt*64 + k];
                float4 w0 = *reinterpret_cast<const float4*>(&Ws[k*H1 + hb]);
                float4 w1 = *reinterpret_cast<const float4*>(&Ws[k*H1 + hb + 4]);
                acc[0] += x*w0.x; acc[1] += x*w0.y; acc[2] += x*w0.z; acc[3] += x*w0.w;
                acc[4] += x*w1.x; acc[5] += x*w1.y; acc[6] += x*w1.z; acc[7] += x*w1.w;
            }
        }
        #pragma unroll
        for (int h = 0; h < 8; h++) {
            float v = acc[h] + fc1b[hb + h];
            v = v > 0.f ? v : 0.01f * v;
            Hs[node*132 + hb + h] = v;
        }
    }

    // ---- phase B: emb = leaky(h @ fc2 + b2), per thread 4 outputs ----
    __syncthreads();
    #pragma unroll
    for (int r = 0; r < 32; r++)       // fc2w: 128*64 = 8192 floats
        Ws[t + r*256] = fc2w[t + r*256];
    __syncthreads();
    {
        const int db = sub * 4;
        float a0 = 0.f, a1 = 0.f, a2 = 0.f, a3 = 0.f;
        #pragma unroll
        for (int k = 0; k < H1; k++) {
            float hv = Hs[node*132 + k];
            float4 w = *reinterpret_cast<const float4*>(&Ws[k*EMBD + db]);
            a0 += hv*w.x; a1 += hv*w.y; a2 += hv*w.z; a3 += hv*w.w;
        }
        float v0 = a0 + fc2b[db+0]; v0 = v0 > 0.f ? v0 : 0.01f*v0;
        float v1 = a1 + fc2b[db+1]; v1 = v1 > 0.f ? v1 : 0.01f*v1;
        float v2 = a2 + fc2b[db+2]; v2 = v2 > 0.f ? v2 : 0.01f*v2;
        float v3 = a3 + fc2b[db+3]; v3 = v3 > 0.f ? v3 : 0.01f*v3;

        Es[node*EMBD + db + 0] = v0;
        Es[node*EMBD + db + 1] = v1;
        Es[node*EMBD + db + 2] = v2;
        Es[node*EMBD + db + 3] = v3;

        const int g = nb + node;
        float4 v4 = make_float4(v0, v1, v2, v3);
        *reinterpret_cast<float4*>(&g_emb[g*EMBD + db]) = v4;
        *reinterpret_cast<float4*>(&out[EMB_OFF + g*EMBD + db]) = v4;

        const int b = g >> 9;
        const int n = g & 511;
        g_embT[(b*EMBD + db + 0)*NN + n] = v0;
        g_embT[(b*EMBD + db + 1)*NN + n] = v1;
        g_embT[(b*EMBD + db + 2)*NN + n] = v2;
        g_embT[(b*EMBD + db + 3)*NN + n] = v3;
    }

    // ---- phase C: A = emb @ e1_w[:64,:], per thread 4 outputs ----
    __syncthreads();
    #pragma unroll
    for (int r = 0; r < 16; r++)       // e1w top half: 64*64 = 4096 floats
        Ws[t + r*256] = e1w[t + r*256];
    __syncthreads();
    {
        const int hb = sub * 4;
        float a0 = 0.f, a1 = 0.f, a2 = 0.f, a3 = 0.f;
        #pragma unroll
        for (int k = 0; k < EMBD; k++) {
            float ev = Es[node*EMBD + k];
            float4 w = *reinterpret_cast<const float4*>(&Ws[k*HE + hb]);
            a0 += ev*w.x; a1 += ev*w.y; a2 += ev*w.z; a3 += ev*w.w;
        }
        const int g = nb + node;
        *reinterpret_cast<float4*>(&g_A[g*HE + hb]) = make_float4(a0, a1, a2, a3);
    }
}

// =====================================================================
// Stage 2: edge MLP over all pairs.
// One block handles 2 source nodes i (same batch). U_i = emb_i⊙W2 − W1.
// pre[j,h] = c_i[h] + emb_j @ U_i ; eh = relu ; d = eh·wdiff + bdiff ;
// p1 = sigmoid(d).  Grid: 1024 blocks x 256 threads.
// =====================================================================
__global__ __launch_bounds__(256, 3)
void stage2(const float* __restrict__ e1w, const float* __restrict__ e1b,
            const float* __restrict__ e2w, const float* __restrict__ e2b,
            float* __restrict__ out)
{
    extern __shared__ float sm[];
    float* U    = sm;               // 2*64*64 = 8192
    float* Et   = U + 8192;         // 64*132  = 8448 (padded pitch)
    float* red  = Et + 8448;        // 8*128   = 1024
    float* cc   = red + 1024;       // 2*64
    float* wd   = cc + 128;         // 64
    float* embi = wd + 64;          // 2*64
    float* bd   = embi + 128;       // 1
    // total = 17985 floats = 71940 B

    const int t   = threadIdx.x;
    const int bid = blockIdx.x;
    const int b   = bid >> 8;            // batch
    const int i0  = (bid & 255) * 2;     // first source node

    if (t < 128) {
        int ii = t >> 6, h = t & 63;
        embi[t] = g_emb[(b*NN + i0 + ii)*EMBD + h];
        cc[t]   = g_A  [(b*NN + i0 + ii)*HE  + h] + e1b[h];
    } else if (t < 192) {
        int h = t - 128;
        wd[h] = e2w[h*2 + 1] - e2w[h*2 + 0];
    } else if (t == 192) {
        *bd = e2b[1] - e2b[0];
    }
    __syncthreads();

    // build U_i[k][h] = emb_i[k]*W2[k][h] - W1[k][h]
    #pragma unroll
    for (int ii = 0; ii < 2; ii++) {
        #pragma unroll
        for (int r = 0; r < 4; r++) {
            int idx = (t + r*256) * 4;     // 0..4095, step 4
            int k   = idx >> 6;
            int h4  = idx & 63;
            float e = embi[ii*64 + k];
            float4 w2 = *reinterpret_cast<const float4*>(&e1w[(64 + k)*HE + h4]);
            float4 w1 = *reinterpret_cast<const float4*>(&e1w[k*HE + h4]);
            float4 u;
            u.x = e*w2.x - w1.x; u.y = e*w2.y - w1.y;
            u.z = e*w2.z - w1.z; u.w = e*w2.w - w1.w;
            *reinterpret_cast<float4*>(&U[ii*4096 + k*64 + h4]) = u;
        }
    }
    __syncthreads();

    const int lane = t & 31;
    const int w    = t >> 5;     // h-group (warp) 0..7
    const int hb   = w * 8;

    float wdr[8];
    #pragma unroll
    for (int h = 0; h < 8; h++) wdr[h] = wd[hb + h];
    const float bdr = *bd;

    for (int chunk = 0; chunk < 4; chunk++) {
        const int jb = chunk * 128;

        // load E^T tile [64 k][128 j] from global (coalesced, conflict-free)
        #pragma unroll
        for (int r = 0; r < 8; r++) {
            int lin = t + r*256;            // 0..2047 float4 units
            int k   = lin >> 5;             // 32 float4 per row
            int j4  = (lin & 31) * 4;
            float4 v = *reinterpret_cast<const float4*>(
                &g_embT[(b*EMBD + k)*NN + jb + j4]);
            *reinterpret_cast<float4*>(&Et[k*132 + j4]) = v;
        }
        __syncthreads();

        for (int ii = 0; ii < 2; ii++) {
            unsigned long long acc[4][4];
            #pragma unroll
            for (int a = 0; a < 4; a++)
                #pragma unroll
                for (int c = 0; c < 4; c++) acc[a][c] = 0ull;

            const float* Ui = &U[ii*4096];

            #pragma unroll 16
            for (int k = 0; k < 64; k++) {
                float4 e = *reinterpret_cast<const float4*>(&Et[k*132 + lane*4]);
                const unsigned long long* up =
                    reinterpret_cast<const unsigned long long*>(&Ui[k*64 + hb]);
                unsigned long long u0 = up[0], u1 = up[1], u2 = up[2], u3 = up[3];
                unsigned long long e0 = pack2(e.x), e1 = pack2(e.y),
                                   e2 = pack2(e.z), e3 = pack2(e.w);
                fma2(acc[0][0], e0, u0); fma2(acc[0][1], e0, u1);
                fma2(acc[0][2], e0, u2); fma2(acc[0][3], e0, u3);
                fma2(acc[1][0], e1, u0); fma2(acc[1][1], e1, u1);
                fma2(acc[1][2], e1, u2); fma2(acc[1][3], e1, u3);
                fma2(acc[2][0], e2, u0); fma2(acc[2][1], e2, u1);
                fma2(acc[2][2], e2, u2); fma2(acc[2][3], e2, u3);
                fma2(acc[3][0], e3, u0); fma2(acc[3][1], e3, u1);
                fma2(acc[3][2], e3, u2); fma2(acc[3][3], e3, u3);
            }

            // epilogue: relu + dot with wdiff, partial over this warp's 8 h
            #pragma unroll
            for (int jj = 0; jj < 4; jj++) {
                float p = 0.f;
                #pragma unroll
                for (int hp = 0; hp < 4; hp++) {
                    float lo, hi;
                    unpack2(acc[jj][hp], lo, hi);
                    float pre0 = lo + cc[ii*64 + hb + hp*2 + 0];
                    float pre1 = hi + cc[ii*64 + hb + hp*2 + 1];
                    pre0 = fmaxf(pre0, 0.f);
                    pre1 = fmaxf(pre1, 0.f);
                    p += pre0 * wdr[hp*2 + 0] + pre1 * wdr[hp*2 + 1];
                }
                red[w*128 + lane*4 + jj] = p;
            }
            __syncthreads();

            if (t < 128) {
                float d = bdr;
                #pragma unroll
                for (int ww = 0; ww < 8; ww++) d += red[ww*128 + t];
                // numerically stable 2-class softmax
                float ad = fabsf(d);
                float ex = __expf(-ad);
                float inv = 1.f / (1.f + ex);
                float pbig = inv, psml = ex * inv;
                float p1 = d >= 0.f ? pbig : psml;
                float p0 = d >= 0.f ? psml : pbig;

                const int ig = i0 + ii;
                const int j  = jb + t;
                out[b*NN*NN + ig*NN + j] = p1;            // adjacency
                if (j != ig) {
                    int kidx = ig*(NN-1) + (j < ig ? j : j - 1);
                    *reinterpret_cast<float2*>(
                        &out[PRED_OFF + (b*NPAIR + kidx)*2]) = make_float2(p0, p1);
                }
            }
            __syncthreads();
        }
    }
}

// =====================================================================
extern "C" void kernel_launch(void* const* d_in, const int* in_sizes, int n_in,
                              void* d_out, int out_size)
{
    (void)in_sizes; (void)n_in; (void)out_size;
    const float* nf   = (const float*)d_in[0];
    const float* fc1w = (const float*)d_in[1];
    const float* fc1b = (const float*)d_in[2];
    const float* fc2w = (const float*)d_in[3];
    const float* fc2b = (const float*)d_in[4];
    const float* e1w  = (const float*)d_in[5];
    const float* e1b  = (const float*)d_in[6];
    const float* e2w  = (const float*)d_in[7];
    const float* e2b  = (const float*)d_in[8];
    float* out = (float*)d_out;

    const int smem1 = 15424 * 4;   // 61696 B
    const int smem2 = 17985 * 4;   // 71940 B
    cudaFuncSetAttribute(stage1, cudaFuncAttributeMaxDynamicSharedMemorySize, smem1);
    cudaFuncSetAttribute(stage2, cudaFuncAttributeMaxDynamicSharedMemorySize, smem2);

    stage1<<<128, 256, smem1>>>(nf, fc1w, fc1b, fc2w, fc2b, e1w, out);
    stage2<<<1024, 256, smem2>>>(e1w, e1b, e2w, e2b, out);
}